// round 2
// baseline (speedup 1.0000x reference)
#include <cuda_runtime.h>

// Problem constants (match reference)
#define KK   16
#define YY   32
#define CC   16
#define SEGS (KK * YY)          // 512 composite bins
#define BINS (SEGS * CC)        // 8192 fp32 accumulators per replica
#define REPL 128                // replicated scratch copies (per-warp assignment)
#define EPSV 1e-8f

// Scratch: 128 * 8192 * 4B = 4 MB. __device__ global => zero-initialized at load.
// finalize_kernel re-zeros it after folding, so every graph replay sees zeros.
__device__ float g_scratch[REPL * BINS];

// ---------------------------------------------------------------------------
// Kernel 1: streaming scatter-accumulate.
// 4 lanes cooperate on one row: each lane loads one float4 of the 16-channel
// row (warp reads 8 consecutive rows = 512 contiguous bytes, 4 L2 lines,
// perfectly coalesced) and issues one no-return float4 global atomic
// (RED.E.128) into this WARP's scratch replica.
// ---------------------------------------------------------------------------
__global__ void accum_kernel(const int* __restrict__ x_labels,
                             const int* __restrict__ y_labels,
                             const float4* __restrict__ post,   // float4 view of [N,16]
                             int nrows) {
    const int tid  = blockIdx.x * blockDim.x + threadIdx.x;
    const int lane = threadIdx.x & 31;
    const int sub  = lane & 3;                       // which float4 of the row

    // per-warp replica: consecutive warps hit different 32KB scratch regions
    float* replica = g_scratch + ((tid >> 5) & (REPL - 1)) * BINS;

    const int rowstride = (gridDim.x * blockDim.x) >> 2;

#pragma unroll 4
    for (int row = tid >> 2; row < nrows; row += rowstride) {
        int seg = 0;
        if (sub == 0) seg = x_labels[row] * YY + y_labels[row];
        seg = __shfl_sync(0xffffffffu, seg, lane & ~3);

        float4 v = post[(size_t)row * 4 + sub];
        float4* dst = reinterpret_cast<float4*>(replica + seg * CC + sub * 4);
        atomicAdd(dst, v);   // sm_90+ vector atomic -> RED.E.128 (no return)
    }
}

// ---------------------------------------------------------------------------
// Kernel 2: fold replicas, re-zero scratch, add eps, normalize over Y.
// Grid = KK blocks, 512 threads each (one per (y, c) pair of that k-slice).
// Each thread zeros exactly the scratch words it folded, so the next graph
// replay's accum_kernel starts from a clean slate (no separate zero kernel).
// ---------------------------------------------------------------------------
__global__ void finalize_kernel(float* __restrict__ out) {
    __shared__ float s_num[YY * CC];

    const int k = blockIdx.x;           // 0..15
    const int t = threadIdx.x;          // 0..511  (t == y*CC + c)
    const int c = t % CC;

    const int bin = k * (YY * CC) + t;
    float num = EPSV;
#pragma unroll 8
    for (int r = 0; r < REPL; r++) {
        num += g_scratch[r * BINS + bin];
        g_scratch[r * BINS + bin] = 0.f;      // re-zero for next replay
    }
    s_num[t] = num;
    __syncthreads();

    float denom = 0.f;
#pragma unroll
    for (int yy = 0; yy < YY; yy++) {
        denom += s_num[yy * CC + c];
    }
    out[bin] = num / denom;
}

// ---------------------------------------------------------------------------
// Launch
// ---------------------------------------------------------------------------
extern "C" void kernel_launch(void* const* d_in, const int* in_sizes, int n_in,
                              void* d_out, int out_size) {
    const int*    x_labels = (const int*)d_in[0];
    const int*    y_labels = (const int*)d_in[1];
    const float4* post     = (const float4*)d_in[2];
    float*        out      = (float*)d_out;

    const int nrows = in_sizes[0];      // N = 4194304

    // 2048 CTAs x 256 threads -> 131072 row-groups x 32 rows each (exact)
    accum_kernel<<<2048, 256>>>(x_labels, y_labels, post, nrows);

    finalize_kernel<<<KK, YY * CC>>>(out);
}

// round 3
// speedup vs baseline: 1.2804x; 1.2804x over previous
#include <cuda_runtime.h>

// Problem constants (match reference)
#define KK   16
#define YY   32
#define CC   16
#define SEGS (KK * YY)          // 512 composite bins
#define BINS (SEGS * CC)        // 8192 fp32 accumulators per replica
#define REPL 128                // replicated scratch copies (per-warp assignment)
#define EPSV 1e-8f

// Scratch: 128 * 8192 * 4B = 4 MB. __device__ global (no allocation in kernel_launch).
__device__ float g_scratch[REPL * BINS];

// ---------------------------------------------------------------------------
// Kernel 0: zero the scratch. 1024 blocks x 256 threads = 262144 threads,
// exactly one float4 store each (4 MB / 16 B). Pure store bandwidth, ~1-2 us.
// ---------------------------------------------------------------------------
__global__ void zero_scratch_kernel() {
    float4* p = reinterpret_cast<float4*>(g_scratch);
    p[blockIdx.x * blockDim.x + threadIdx.x] = make_float4(0.f, 0.f, 0.f, 0.f);
}

// ---------------------------------------------------------------------------
// Kernel 1: streaming scatter-accumulate (UNCHANGED from round 2 — measured
// ~42 us, 86% of the 36 us DRAM floor).
// 4 lanes cooperate on one row: each lane loads one float4 of the 16-channel
// row (warp reads 8 consecutive rows = 512 contiguous bytes, coalesced) and
// issues one no-return float4 global atomic (RED.E.128) into this WARP's
// scratch replica.
// ---------------------------------------------------------------------------
__global__ void accum_kernel(const int* __restrict__ x_labels,
                             const int* __restrict__ y_labels,
                             const float4* __restrict__ post,   // float4 view of [N,16]
                             int nrows) {
    const int tid  = blockIdx.x * blockDim.x + threadIdx.x;
    const int lane = threadIdx.x & 31;
    const int sub  = lane & 3;                       // which float4 of the row

    // per-warp replica: consecutive warps hit different 32KB scratch regions
    float* replica = g_scratch + ((tid >> 5) & (REPL - 1)) * BINS;

    const int rowstride = (gridDim.x * blockDim.x) >> 2;

#pragma unroll 4
    for (int row = tid >> 2; row < nrows; row += rowstride) {
        int seg = 0;
        if (sub == 0) seg = x_labels[row] * YY + y_labels[row];
        seg = __shfl_sync(0xffffffffu, seg, lane & ~3);

        float4 v = post[(size_t)row * 4 + sub];
        float4* dst = reinterpret_cast<float4*>(replica + seg * CC + sub * 4);
        atomicAdd(dst, v);   // sm_90+ vector atomic -> RED.E.128 (no return)
    }
}

// ---------------------------------------------------------------------------
// Kernel 2: fold replicas + add eps + normalize over Y. PURE READ of scratch.
// Grid = 16 blocks (one per k), 1024 threads.
//   Per k-slice: 32 segs x 4 float4-chunks = 128 float4 bins, x 128 replicas.
//   Thread t: bin4 = t & 127, replica-chunk = t >> 7 (8 chunks of 16).
//   Each thread sums 16 independent L2-resident float4 loads -> smem,
//   8-way tree reduce over chunks, then Y-normalization in smem.
// ---------------------------------------------------------------------------
__global__ void finalize_kernel(float* __restrict__ out) {
    __shared__ float4 s_part[1024];      // [chunk(8)][bin4(128)]

    const int k    = blockIdx.x;         // 0..15
    const int t    = threadIdx.x;        // 0..1023
    const int bin4 = t & 127;            // which float4 of the k-slice
    const int rch  = t >> 7;             // replica chunk 0..7

    // float4 index of this bin within a replica: k-slice starts at k*512 floats
    const float4* base = reinterpret_cast<const float4*>(g_scratch) + k * 128 + bin4;

    float4 acc = make_float4(0.f, 0.f, 0.f, 0.f);
#pragma unroll
    for (int r = 0; r < 16; r++) {
        // replica (rch*16 + r), stride BINS floats = 2048 float4s
        float4 v = base[(rch * 16 + r) * (BINS / 4)];
        acc.x += v.x; acc.y += v.y; acc.z += v.z; acc.w += v.w;
    }
    s_part[rch * 128 + bin4] = acc;
    __syncthreads();

    // tree-reduce the 8 replica chunks
#pragma unroll
    for (int step = 4; step >= 1; step >>= 1) {
        if (rch < step) {
            float4 a = s_part[rch * 128 + bin4];
            float4 b = s_part[(rch + step) * 128 + bin4];
            a.x += b.x; a.y += b.y; a.z += b.z; a.w += b.w;
            s_part[rch * 128 + bin4] = a;
        }
        __syncthreads();
    }

    // first 128 threads: numerator (+eps) now in s_part[0..127]; normalize over Y
    if (t < 128) {
        const int sub = bin4 & 3;        // float4 chunk within a segment (channels sub*4..)
        float4 num = s_part[bin4];
        num.x += EPSV; num.y += EPSV; num.z += EPSV; num.w += EPSV;
        s_part[bin4] = num;              // safe: only threads <128 touch it now
        __syncwarp();                     // not enough: cross-warp...
    }
    __syncthreads();
    if (t < 128) {
        const int sub = bin4 & 3;
        float4 num = s_part[bin4];
        float4 den = make_float4(0.f, 0.f, 0.f, 0.f);
#pragma unroll
        for (int yy = 0; yy < YY; yy++) {
            float4 v = s_part[yy * 4 + sub];
            den.x += v.x; den.y += v.y; den.z += v.z; den.w += v.w;
        }
        float4 r;
        r.x = num.x / den.x; r.y = num.y / den.y;
        r.z = num.z / den.z; r.w = num.w / den.w;
        reinterpret_cast<float4*>(out)[k * 128 + bin4] = r;
    }
}

// ---------------------------------------------------------------------------
// Launch
// ---------------------------------------------------------------------------
extern "C" void kernel_launch(void* const* d_in, const int* in_sizes, int n_in,
                              void* d_out, int out_size) {
    const int*    x_labels = (const int*)d_in[0];
    const int*    y_labels = (const int*)d_in[1];
    const float4* post     = (const float4*)d_in[2];
    float*        out      = (float*)d_out;

    const int nrows = in_sizes[0];      // N = 4194304

    zero_scratch_kernel<<<1024, 256>>>();

    // 2048 CTAs x 256 threads -> 131072 row-groups x 32 rows each (exact)
    accum_kernel<<<2048, 256>>>(x_labels, y_labels, post, nrows);

    finalize_kernel<<<KK, 1024>>>(out);
}

// round 4
// speedup vs baseline: 1.4172x; 1.1069x over previous
#include <cuda_runtime.h>

// Problem constants (match reference)
#define KK   16
#define YY   32
#define CC   16
#define SEGS (KK * YY)          // 512 composite bins
#define BINS (SEGS * CC)        // 8192 fp32 accumulators per replica
#define REPL 64                 // replicated scratch copies (per-warp assignment)
#define EPSV 1e-8f

// Scratch: 64 * 8192 * 4B = 2 MB. __device__ global (no allocation anywhere).
__device__ float g_scratch[REPL * BINS];

// ---------------------------------------------------------------------------
// Kernel 1: streaming scatter-accumulate.
// Grid = 1184 CTAs (148 SMs x 8 CTAs of 256 threads = exactly one resident
// wave; the old 2048-CTA grid ran as 1184 + a 864-CTA serial tail = 1.73x).
// 4 lanes cooperate on one row: each lane loads one float4 of the 16-channel
// row (warp reads 8 consecutive rows = 512 contiguous bytes, coalesced) and
// issues one no-return float4 global atomic (RED.E.128) into this WARP's
// scratch replica.
// ---------------------------------------------------------------------------
__global__ void __launch_bounds__(256)
accum_kernel(const int* __restrict__ x_labels,
             const int* __restrict__ y_labels,
             const float4* __restrict__ post,   // float4 view of [N,16]
             int nrows) {
    const int tid  = blockIdx.x * blockDim.x + threadIdx.x;
    const int lane = threadIdx.x & 31;
    const int sub  = lane & 3;                       // which float4 of the row

    // per-warp replica: consecutive warps hit different 32KB scratch regions
    float* replica = g_scratch + ((tid >> 5) & (REPL - 1)) * BINS;

    const int rowstride = (gridDim.x * blockDim.x) >> 2;

#pragma unroll 4
    for (int row = tid >> 2; row < nrows; row += rowstride) {
        int seg = 0;
        if (sub == 0) seg = x_labels[row] * YY + y_labels[row];
        seg = __shfl_sync(0xffffffffu, seg, lane & ~3);

        float4 v = post[(size_t)row * 4 + sub];
        float4* dst = reinterpret_cast<float4*>(replica + seg * CC + sub * 4);
        atomicAdd(dst, v);   // sm_90+ vector atomic -> RED.E.128 (no return)
    }
}

// ---------------------------------------------------------------------------
// Kernel 2: fold replicas + add eps + normalize over Y. PURE READ of scratch.
// Grid = 16 blocks (one per k), 1024 threads.
//   Per k-slice: 32 segs x 4 float4-chunks = 128 float4 bins, x 64 replicas.
//   Thread t: bin4 = t & 127, replica-chunk rch = t >> 7 (8 chunks of 8).
//   Each thread sums 8 independent float4 loads -> smem, 8-way tree reduce,
//   then the Y-normalization in smem.
// ---------------------------------------------------------------------------
__global__ void finalize_kernel(float* __restrict__ out) {
    __shared__ float4 s_part[1024];      // [chunk(8)][bin4(128)]

    const int k    = blockIdx.x;         // 0..15
    const int t    = threadIdx.x;        // 0..1023
    const int bin4 = t & 127;            // which float4 of the k-slice
    const int rch  = t >> 7;             // replica chunk 0..7

    const float4* base = reinterpret_cast<const float4*>(g_scratch) + k * 128 + bin4;

    float4 acc = make_float4(0.f, 0.f, 0.f, 0.f);
#pragma unroll
    for (int r = 0; r < 8; r++) {
        float4 v = base[(rch * 8 + r) * (BINS / 4)];   // stride 32KB
        acc.x += v.x; acc.y += v.y; acc.z += v.z; acc.w += v.w;
    }
    s_part[rch * 128 + bin4] = acc;
    __syncthreads();

#pragma unroll
    for (int step = 4; step >= 1; step >>= 1) {
        if (rch < step) {
            float4 a = s_part[rch * 128 + bin4];
            float4 b = s_part[(rch + step) * 128 + bin4];
            a.x += b.x; a.y += b.y; a.z += b.z; a.w += b.w;
            s_part[rch * 128 + bin4] = a;
        }
        __syncthreads();
    }

    // s_part[0..127] holds the folded numerators for this k-slice.
    if (t < 128) {
        float4 num = s_part[bin4];
        num.x += EPSV; num.y += EPSV; num.z += EPSV; num.w += EPSV;
        s_part[bin4] = num;
    }
    __syncthreads();
    if (t < 128) {
        const int sub = bin4 & 3;        // float4 chunk within a segment
        float4 num = s_part[bin4];
        float4 den = make_float4(0.f, 0.f, 0.f, 0.f);
#pragma unroll
        for (int yy = 0; yy < YY; yy++) {
            float4 v = s_part[yy * 4 + sub];
            den.x += v.x; den.y += v.y; den.z += v.z; den.w += v.w;
        }
        float4 r;
        r.x = num.x / den.x; r.y = num.y / den.y;
        r.z = num.z / den.z; r.w = num.w / den.w;
        reinterpret_cast<float4*>(out)[k * 128 + bin4] = r;
    }
}

// ---------------------------------------------------------------------------
// Launch
// ---------------------------------------------------------------------------
extern "C" void kernel_launch(void* const* d_in, const int* in_sizes, int n_in,
                              void* d_out, int out_size) {
    const int*    x_labels = (const int*)d_in[0];
    const int*    y_labels = (const int*)d_in[1];
    const float4* post     = (const float4*)d_in[2];
    float*        out      = (float*)d_out;

    const int nrows = in_sizes[0];      // N = 4194304

    // Zero the scratch via a memset node (graph-capturable, no allocation).
    void* scratch_ptr = nullptr;
    cudaGetSymbolAddress(&scratch_ptr, g_scratch);
    cudaMemsetAsync(scratch_ptr, 0, REPL * BINS * sizeof(float));

    // 1184 CTAs x 256 threads = 148 SMs x 8 resident CTAs: single wave.
    accum_kernel<<<1184, 256>>>(x_labels, y_labels, post, nrows);

    finalize_kernel<<<KK, 1024>>>(out);
}